// round 13
// baseline (speedup 1.0000x reference)
#include <cuda_runtime.h>
#include <cuda_bf16.h>

// ---------------------------------------------------------------------------
// Problem constants (fixed by the dataset)
// ---------------------------------------------------------------------------
#define S_LEN   256
#define BSZ     64
#define IN_DIM  128
#define HID     128
#define NT      2
#define TAPELEN 128
#define DIM     64          // HID / NT
#define LH      64          // HID / 2
#define G4      256         // 4 * LH

#define N_ROWS  (S_LEN * BSZ)          // 16384

// d_out layout: outputs [S,B,HID], tape [TL,B,NT,DIM], rpos [TL,B,NT], wpos [TL,B,NT]
#define OUT_OUTPUTS_SZ  (S_LEN * BSZ * HID)                 // 2097152
#define OUT_TAPE_OFF    (OUT_OUTPUTS_SZ)
#define OUT_TAPE_SZ     (TAPELEN * BSZ * NT * DIM)          // 1048576
#define OUT_RPOS_OFF    (OUT_TAPE_OFF + OUT_TAPE_SZ)
#define OUT_POS_SZ      (TAPELEN * BSZ * NT)                // 16384
#define OUT_WPOS_OFF    (OUT_RPOS_OFF + OUT_POS_SZ)
#define OUT_TOTAL       (OUT_WPOS_OFF + OUT_POS_SZ)

typedef unsigned long long u64;

// ---------------------------------------------------------------------------
// f32x2 packed-math helpers (Blackwell FFMA2 path — PTX only)
// ---------------------------------------------------------------------------
__device__ __forceinline__ u64 pack2(float x, float y) {
    u64 r; asm("mov.b64 %0, {%1, %2};" : "=l"(r) : "f"(x), "f"(y)); return r;
}
__device__ __forceinline__ u64 dup2(float x) { return pack2(x, x); }
__device__ __forceinline__ void unpack2(u64 v, float& x, float& y) {
    asm("mov.b64 {%0, %1}, %2;" : "=f"(x), "=f"(y) : "l"(v));
}
__device__ __forceinline__ u64 ffma2(u64 a, u64 b, u64 c) {
    u64 d; asm("fma.rn.f32x2 %0, %1, %2, %3;" : "=l"(d) : "l"(a), "l"(b), "l"(c)); return d;
}
__device__ __forceinline__ u64 fadd2(u64 a, u64 b) {
    u64 d; asm("add.rn.f32x2 %0, %1, %2;" : "=l"(d) : "l"(a), "l"(b)); return d;
}
__device__ __forceinline__ u64 fmul2(u64 a, u64 b) {
    u64 d; asm("mul.rn.f32x2 %0, %1, %2;" : "=l"(d) : "l"(a), "l"(b)); return d;
}
__device__ __forceinline__ u64 shflx_u64(u64 v, int m) {
    float x, y; unpack2(v, x, y);
    x = __shfl_xor_sync(0xffffffffu, x, m);
    y = __shfl_xor_sync(0xffffffffu, y, m);
    return pack2(x, y);
}

__device__ __forceinline__ float sigmoidf_(float x) {
    return 1.0f / (1.0f + __expf(-x));
}
// tanh(x) = 2*sigmoid(2x) - 1  — MUFU-based, NaN-free at +/- inf
__device__ __forceinline__ float tanh_fast(float x) {
    return 2.0f / (1.0f + __expf(-2.0f * x)) - 1.0f;
}

// ---------------------------------------------------------------------------
// Scratch (device globals — no allocations allowed)
// ---------------------------------------------------------------------------
__device__ float g_xproj_f[N_ROWS * G4];     // 16.8 MB
__device__ float g_xproj_r[N_ROWS * G4];     // 16.8 MB
__device__ float g_values [N_ROWS * HID];    //  8.4 MB
__device__ float g_hidden [N_ROWS * HID];    //  8.4 MB
__device__ float g_params [N_ROWS * NT * 8]; //  1.0 MB
__device__ float g_readout[N_ROWS * HID];    //  8.4 MB
__device__ float g_posw  [BSZ * NT * S_LEN * TAPELEN];   // 16.8 MB
__device__ float g_posr  [BSZ * NT * S_LEN * TAPELEN];   // 16.8 MB

// ---------------------------------------------------------------------------
// GEMM core: C[M,N] = A[M,128] * B[N,128]^T + bias1[N] (+ bias2[N])
// ---------------------------------------------------------------------------
__device__ __forceinline__ void gemm_tile(
    const float* __restrict__ A, const float* __restrict__ B,
    const float* __restrict__ b1, const float* __restrict__ b2,
    float* __restrict__ C, int N, int row0, int col0)
{
    __shared__ __align__(16) float As[32][130];
    __shared__ __align__(16) float Bs[32][65];

    int tid = threadIdx.x;
    int tx = tid & 15;          // col group (4 cols)
    int ty = tid >> 4;          // row group (8 rows)

    const float4* A4 = (const float4*)A;
    const float4* B4 = (const float4*)B;

    u64 acc[4][4];
#pragma unroll
    for (int i = 0; i < 4; i++)
#pragma unroll
        for (int j = 0; j < 4; j++) acc[i][j] = 0ull;

#pragma unroll
    for (int kt = 0; kt < 4; kt++) {
#pragma unroll
        for (int rep = 0; rep < 4; rep++) {
            int e = tid + 256 * rep;
            int r = e >> 3, k4 = e & 7;
            float4 v = A4[(size_t)(row0 + r) * 32 + kt * 8 + k4];
            As[k4 * 4 + 0][r] = v.x; As[k4 * 4 + 1][r] = v.y;
            As[k4 * 4 + 2][r] = v.z; As[k4 * 4 + 3][r] = v.w;
        }
#pragma unroll
        for (int rep = 0; rep < 2; rep++) {
            int e = tid + 256 * rep;
            int r = e >> 3, k4 = e & 7;
            float4 v = B4[(size_t)(col0 + r) * 32 + kt * 8 + k4];
            Bs[k4 * 4 + 0][r] = v.x; Bs[k4 * 4 + 1][r] = v.y;
            Bs[k4 * 4 + 2][r] = v.z; Bs[k4 * 4 + 3][r] = v.w;
        }
        __syncthreads();

#pragma unroll
        for (int kk = 0; kk < 32; kk++) {
            u64 a2[4];
#pragma unroll
            for (int ip = 0; ip < 4; ip++)
                a2[ip] = *(const u64*)&As[kk][ty * 8 + 2 * ip];
#pragma unroll
            for (int j = 0; j < 4; j++) {
                u64 bd = dup2(Bs[kk][tx * 4 + j]);
#pragma unroll
                for (int ip = 0; ip < 4; ip++)
                    acc[ip][j] = ffma2(a2[ip], bd, acc[ip][j]);
            }
        }
        __syncthreads();
    }

#pragma unroll
    for (int j = 0; j < 4; j++) {
        int col = col0 + tx * 4 + j;
        float bv = b1[col] + (b2 ? b2[col] : 0.0f);
#pragma unroll
        for (int ip = 0; ip < 4; ip++) {
            float x, y; unpack2(acc[ip][j], x, y);
            int row = row0 + ty * 8 + 2 * ip;
            C[(size_t)row * N + col]       = x + bv;
            C[(size_t)(row + 1) * N + col] = y + bv;
        }
    }
}

// Fused input projections: 3 GEMMs (f-gates 256 cols, r-gates 256 cols, values 128 cols)
__global__ __launch_bounds__(256) void gemm_fused_in(
    const float* __restrict__ A,
    const float* __restrict__ Wf, const float* __restrict__ bf1, const float* __restrict__ bf2,
    const float* __restrict__ Wr, const float* __restrict__ br1, const float* __restrict__ br2,
    const float* __restrict__ Wv, const float* __restrict__ bv1,
    float* __restrict__ Cf, float* __restrict__ Cr, float* __restrict__ Cv)
{
    int cb = blockIdx.x;            // 0..9
    int row0 = blockIdx.y * 128;
    if (cb < 4)      gemm_tile(A, Wf, bf1, bf2,     Cf, G4,  row0, cb * 64);
    else if (cb < 8) gemm_tile(A, Wr, br1, br2,     Cr, G4,  row0, (cb - 4) * 64);
    else             gemm_tile(A, Wv, bv1, nullptr, Cv, HID, row0, (cb - 8) * 64);
}

__global__ __launch_bounds__(256) void gemm_k128(
    const float* __restrict__ A, const float* __restrict__ B,
    const float* __restrict__ b1, float* __restrict__ C, int N)
{
    gemm_tile(A, B, b1, nullptr, C, N, blockIdx.y * 128, blockIdx.x * 64);
}

// ---------------------------------------------------------------------------
// Kernel 2: bidirectional LSTM recurrence — SINGLE-BARRIER design.
// One block per (batch, direction). tid = j*4 + q: all 4 gates (q: i,f,g,o)
// of hidden unit j live in the SAME WARP (warp = 8 units). After per-gate
// nonlinearity, activations are exchanged via 3 intra-warp shuffles; lane
// q==0 updates c,h. h double-buffered in smem -> ONE __syncthreads per step.
// ---------------------------------------------------------------------------
__global__ __launch_bounds__(256) void lstm_k(
    const float* __restrict__ xpf, const float* __restrict__ xpr,
    const float* __restrict__ Whh_f, const float* __restrict__ Whh_r,
    float* __restrict__ hidden)
{
    int b   = blockIdx.x & 63;
    int dir = blockIdx.x >> 6;
    int tid = threadIdx.x;
    int j   = tid >> 2;          // hidden unit (0..63)
    int q   = tid & 3;           // gate type: 0=i, 1=f, 2=g, 3=o
    int row = q * 64 + j;        // W_hh row / xp column

    const float* Whh = dir ? Whh_r : Whh_f;
    const float* xp  = dir ? xpr   : xpf;

    u64 w2[32];
    const u64* wrow = (const u64*)(Whh + (size_t)row * 64);
#pragma unroll
    for (int k = 0; k < 32; k++) w2[k] = wrow[k];

    __shared__ __align__(16) float h_sm[2][64];
    if (tid < 64) h_sm[0][tid] = 0.0f;
    float c = 0.0f;
    __syncthreads();

    const float* xbase = xp + (size_t)b * G4 + row;

    int s   = dir ? (S_LEN - 1) : 0;
    int stp = dir ? -1 : 1;
    float gn = __ldg(&xbase[(size_t)s * (BSZ * G4)]);   // prefetch step 0

    int lane = tid & 31;
    int lbase = lane & ~3;       // lane of q==0 for this unit

    int cur = 0;
    for (int ss = 0; ss < S_LEN; ss++) {
        float g = gn;
        int s_cur = s;
        s += stp;
        if (ss + 1 < S_LEN)
            gn = __ldg(&xbase[(size_t)s * (BSZ * G4)]);  // prefetch next step

        const u64* h2 = (const u64*)h_sm[cur];
        u64 a0 = 0ull, a1 = 0ull, a2 = 0ull, a3 = 0ull;
#pragma unroll
        for (int k = 0; k < 32; k += 4) {
            a0 = ffma2(w2[k + 0], h2[k + 0], a0);
            a1 = ffma2(w2[k + 1], h2[k + 1], a1);
            a2 = ffma2(w2[k + 2], h2[k + 2], a2);
            a3 = ffma2(w2[k + 3], h2[k + 3], a3);
        }
        u64 at = fadd2(fadd2(a0, a1), fadd2(a2, a3));
        float sx, sy; unpack2(at, sx, sy);
        g += sx + sy;

        float av = (q == 2) ? tanh_fast(g) : sigmoidf_(g);

        // exchange gate activations within the warp (unit-local)
        float av_f = __shfl_sync(0xffffffffu, av, lbase + 1);
        float av_g = __shfl_sync(0xffffffffu, av, lbase + 2);
        float av_o = __shfl_sync(0xffffffffu, av, lbase + 3);

        if (q == 0) {
            // av == sigma(i)
            c = av_f * c + av * av_g;
            float h = av_o * tanh_fast(c);
            h_sm[cur ^ 1][j] = h;
            hidden[(size_t)(s_cur * BSZ + b) * HID + dir * 64 + j] = h;
        }
        __syncthreads();
        cur ^= 1;
    }
}

// ---------------------------------------------------------------------------
// Kernel 3: action head + nonlinearities. One thread per (row, tape).
// params[row][t][8] = {rd0,rd1,rd2, wd0,wd1,wd2, rw_read, rw_write}
// ---------------------------------------------------------------------------
__global__ __launch_bounds__(256) void act_k(
    const float* __restrict__ hidden, const float* __restrict__ Wact,
    const float* __restrict__ bact, float* __restrict__ params)
{
    int gt  = blockIdx.x * 256 + threadIdx.x;   // 0 .. 32767
    int row = gt >> 1;
    int t   = gt & 1;

    const float4* h4 = (const float4*)(hidden + (size_t)row * HID);
    const float4* w4 = (const float4*)Wact;

    float acc[8];
#pragma unroll
    for (int jj = 0; jj < 8; jj++) acc[jj] = 0.0f;

#pragma unroll 4
    for (int k4 = 0; k4 < 32; k4++) {
        float4 h = __ldg(&h4[k4]);
#pragma unroll
        for (int jj = 0; jj < 8; jj++) {
            float4 w = __ldg(&w4[(t * 8 + jj) * 32 + k4]);
            acc[jj] += h.x * w.x + h.y * w.y + h.z * w.z + h.w * w.w;
        }
    }
#pragma unroll
    for (int jj = 0; jj < 8; jj++) acc[jj] += bact[t * 8 + jj];

    float out[8];
    float m = fmaxf(acc[0], fmaxf(acc[1], acc[2]));
    float e0 = __expf(acc[0] - m), e1 = __expf(acc[1] - m), e2 = __expf(acc[2] - m);
    float inv = 1.0f / (e0 + e1 + e2);
    out[0] = e0 * inv; out[1] = e1 * inv; out[2] = e2 * inv;
    m = fmaxf(acc[3], fmaxf(acc[4], acc[5]));
    e0 = __expf(acc[3] - m); e1 = __expf(acc[4] - m); e2 = __expf(acc[5] - m);
    inv = 1.0f / (e0 + e1 + e2);
    out[3] = e0 * inv; out[4] = e1 * inv; out[5] = e2 * inv;
    out[6] = sigmoidf_(acc[6]);
    out[7] = sigmoidf_(acc[7]);

    float4* p4 = (float4*)(params + (size_t)gt * 8);
    p4[0] = make_float4(out[0], out[1], out[2], out[3]);
    p4[1] = make_float4(out[4], out[5], out[6], out[7]);
}

// ---------------------------------------------------------------------------
// Kernel 4: FUSED tape machine — one block per (b,t), 256 threads.
//   Phase A (warp 0): serial position scan (params staged in smem overlay),
//                     positions -> global posw/posr, final pos -> d_out.
//   Phase B: sw_s = dot(wpos_s, rpos_s) from global positions; cached in smem.
//   Phase C: chunked tape scan. Positions staged in smem PRE-DUPLICATED as
//            f32x2 (u64) per 8-step chunk (double-buffered), conflict-free.
// ---------------------------------------------------------------------------
#define TCHUNK 8
#define NCHUNK (S_LEN / TCHUNK)

__global__ __launch_bounds__(256) void tape_k(
    const float* __restrict__ values, const float* __restrict__ params,
    float* __restrict__ posw, float* __restrict__ posr,
    float* __restrict__ readouts, float* __restrict__ out_tape,
    float* __restrict__ out_rpos, float* __restrict__ out_wpos)
{
    int bt = blockIdx.x;            // b*2 + t
    int b  = bt >> 1;
    int t  = bt & 1;

    int tid  = threadIdx.x;         // 0..255
    int w    = tid >> 5;            // warp 0..7
    int lane = tid & 31;
    int cg   = lane >> 3;           // group within warp (0..3)
    int r    = lane & 7;            // lane-row within group
    int cp   = 4 * w + cg;          // column pair owned (0..31)

    __shared__ __align__(16) u64 pws[2][TCHUNK][TAPELEN];   // 16 KB (dup'd wpos)
    __shared__ __align__(16) u64 prs[2][TCHUNK][TAPELEN];   // 16 KB (dup'd rpos)
    __shared__ __align__(16) float vls[2][TCHUNK][64];      //  4 KB
    __shared__ float swv[S_LEN], rw0v[S_LEN], rw1v[S_LEN];  //  3 KB
    // params overlay lives in pws[0] (8 KB) during phases A/B only
    float4* psm = (float4*)&pws[0][0][0];                   // [S_LEN*2]

    float* gw = posw + (size_t)bt * S_LEN * TAPELEN;
    float* gr = posr + (size_t)bt * S_LEN * TAPELEN;

    // ---- Phase A: stage params; warp 0 runs the serial position scan ----
    {
        const float4* pb = (const float4*)(params + (((size_t)b * 2) + t) * 8);
        for (int e = tid; e < S_LEN * 2; e += 256) {
            int s = e >> 1, half = e & 1;
            psm[s * 2 + half] = __ldg(&pb[(size_t)s * 256 + half]);
        }
    }
    __syncthreads();

    if (w == 0) {
        int pl0 = 4 * lane;
        float wp[4], rp[4];
#pragma unroll
        for (int i = 0; i < 4; i++) {
            float v = (lane == 0 && i == 0) ? 1.0f : 0.0f;
            wp[i] = v; rp[i] = v;
        }
        int src_up = (lane + 1) & 31;
        int src_dn = (lane - 1) & 31;

        for (int s = 0; s < S_LEN; s++) {
            *(float4*)(gw + (size_t)s * TAPELEN + pl0) = make_float4(wp[0], wp[1], wp[2], wp[3]);
            *(float4*)(gr + (size_t)s * TAPELEN + pl0) = make_float4(rp[0], rp[1], rp[2], rp[3]);

            float4 pp0 = psm[s * 2];
            float4 pp1 = psm[s * 2 + 1];

            float rtop = __shfl_sync(0xffffffffu, rp[0], src_up);   // rpos[pl0+4 mod 128]
            float rbot = __shfl_sync(0xffffffffu, rp[3], src_dn);   // rpos[pl0-1 mod 128]
            float rd0 = pp0.x, rd1 = pp0.y, rd2 = pp0.z;
            float wd0 = pp0.w, wd1 = pp1.x, wd2 = pp1.y;

            float prev = rbot;
#pragma unroll
            for (int i = 0; i < 4; i++) {
                float cur  = rp[i];
                float next = (i < 3) ? rp[i + 1] : rtop;
                // wpos'[l] = rpos[l+1]*wd0 + wpos[l]*wd1 + rpos[l-1]*wd2
                wp[i] = fmaf(next, wd0, fmaf(wp[i], wd1, prev * wd2));
                // rpos'[l] = rpos[l+1]*rd0 + rpos[l]*rd1 + rpos[l-1]*rd2
                rp[i] = fmaf(next, rd0, fmaf(cur,  rd1, prev * rd2));
                prev = cur;
            }
        }

        if (out_rpos) {
#pragma unroll
            for (int i = 0; i < 4; i++) {
                int l = pl0 + i;
                out_rpos[(size_t)(l * BSZ + b) * 2 + t] = rp[i];
                out_wpos[(size_t)(l * BSZ + b) * 2 + t] = wp[i];
            }
        }
    }
    __syncthreads();   // positions visible to all warps (in-block coherence)

    // ---- Phase B: sw_s for 256 steps (32 steps per warp) ----
    for (int i = 0; i < 32; i++) {
        int s = w * 32 + i;
        float4 wv = *(const float4*)(gw + (size_t)s * TAPELEN + lane * 4);
        float4 rv = *(const float4*)(gr + (size_t)s * TAPELEN + lane * 4);
        float d = wv.x * rv.x + wv.y * rv.y + wv.z * rv.z + wv.w * rv.w;
#pragma unroll
        for (int m = 1; m <= 16; m <<= 1)
            d += __shfl_xor_sync(0xffffffffu, d, m);
        if (lane == 0) {
            float4 p1 = psm[s * 2 + 1];
            swv[s] = d; rw0v[s] = p1.z; rw1v[s] = p1.w;
        }
    }
    __syncthreads();   // psm (pws[0]) free to be overwritten from here

    // ---- Phase C: chunked tape scan ----
    u64 tp[16];
#pragma unroll
    for (int i = 0; i < 16; i++) tp[i] = 0ull;

    float* ro = readouts + (size_t)b * HID + t * 64 + 2 * cp;

    float4 wstg, rstg, vstg;
    int st_ls = tid >> 5, st_q = tid & 31;
    int sv_ls = tid >> 4, sv_q = tid & 15;

    // load + commit chunk 0
    {
        wstg = __ldg((const float4*)gw + tid);
        rstg = __ldg((const float4*)gr + tid);
        if (tid < 128)
            vstg = __ldg((const float4*)(values + ((size_t)sv_ls * BSZ + b) * HID + t * 64) + sv_q);
        u64* pwd = &pws[0][st_ls][4 * st_q];
        u64* prd = &prs[0][st_ls][4 * st_q];
        pwd[0] = dup2(wstg.x); pwd[1] = dup2(wstg.y); pwd[2] = dup2(wstg.z); pwd[3] = dup2(wstg.w);
        prd[0] = dup2(rstg.x); prd[1] = dup2(rstg.y); prd[2] = dup2(rstg.z); prd[3] = dup2(rstg.w);
        if (tid < 128) *(float4*)&vls[0][sv_ls][4 * sv_q] = vstg;
    }
    __syncthreads();

    for (int c = 0; c < NCHUNK; c++) {
        int buf = c & 1;

        // issue global loads for chunk c+1 (hidden under compute)
        if (c + 1 < NCHUNK) {
            size_t s0 = (size_t)(c + 1) * TCHUNK;
            wstg = __ldg((const float4*)(gw + s0 * TAPELEN) + tid);
            rstg = __ldg((const float4*)(gr + s0 * TAPELEN) + tid);
            if (tid < 128)
                vstg = __ldg((const float4*)(values + ((s0 + sv_ls) * BSZ + b) * HID + t * 64) + sv_q);
        }

        // compute 8 steps from smem
#pragma unroll 2
        for (int ls = 0; ls < TCHUNK; ls++) {
            int s = c * TCHUNK + ls;

            u64 val2 = *(const u64*)&vls[buf][ls][2 * cp];

            u64 wl[16];
            u64 owp = 0ull, orp = 0ull;
#pragma unroll
            for (int k = 0; k < 8; k++) {
                ulonglong2 wv = *(const ulonglong2*)&pws[buf][ls][16 * k + 2 * r];
                ulonglong2 rv = *(const ulonglong2*)&prs[buf][ls][16 * k + 2 * r];
                wl[2 * k]     = wv.x;
                wl[2 * k + 1] = wv.y;
                owp = ffma2(tp[2 * k],     wv.x, owp);
                owp = ffma2(tp[2 * k + 1], wv.y, owp);
                orp = ffma2(tp[2 * k],     rv.x, orp);
                orp = ffma2(tp[2 * k + 1], rv.y, orp);
            }
            // butterfly reduce over the 8-lane group (3 rounds)
#pragma unroll
            for (int m = 1; m <= 4; m <<= 1) {
                owp = fadd2(owp, shflx_u64(owp, m));
                orp = fadd2(orp, shflx_u64(orp, m));
            }

            float sw = swv[s], rw0 = rw0v[s], rw1 = rw1v[s];
            u64 d2  = fmul2(ffma2(owp, dup2(-1.0f), val2), dup2(rw1));
            u64 ro2 = fmul2(ffma2(d2, dup2(sw), orp), dup2(rw0));
            if (r == 0) {
                float rox, roy; unpack2(ro2, rox, roy);
                *(float2*)(ro + (size_t)s * (BSZ * HID)) = make_float2(rox, roy);
            }

            // tape update (register rank-1)
#pragma unroll
            for (int i = 0; i < 16; i++)
                tp[i] = ffma2(wl[i], d2, tp[i]);
        }

        // commit staged chunk c+1 into the other buffer
        if (c + 1 < NCHUNK) {
            int nb = buf ^ 1;
            u64* pwd = &pws[nb][st_ls][4 * st_q];
            u64* prd = &prs[nb][st_ls][4 * st_q];
            pwd[0] = dup2(wstg.x); pwd[1] = dup2(wstg.y); pwd[2] = dup2(wstg.z); pwd[3] = dup2(wstg.w);
            prd[0] = dup2(rstg.x); prd[1] = dup2(rstg.y); prd[2] = dup2(rstg.z); prd[3] = dup2(rstg.w);
            if (tid < 128) *(float4*)&vls[nb][sv_ls][4 * sv_q] = vstg;
        }
        __syncthreads();
    }

    // final tape -> d_out  (level l = 16k + 2r + j, tp index 2k+j)
    if (out_tape) {
#pragma unroll
        for (int k = 0; k < 8; k++) {
#pragma unroll
            for (int j = 0; j < 2; j++) {
                int l = 16 * k + 2 * r + j;
                float x, y; unpack2(tp[2 * k + j], x, y);
                *(float2*)(out_tape + ((size_t)(l * BSZ + b) * 2 + t) * 64 + 2 * cp) =
                    make_float2(x, y);
            }
        }
    }
}

// ---------------------------------------------------------------------------
// Launcher — 5 launches; tape_k is launch index 3 (the one ncu captures).
// ---------------------------------------------------------------------------
extern "C" void kernel_launch(void* const* d_in, const int* in_sizes, int n_in,
                              void* d_out, int out_size)
{
    const float* inputs = (const float*)d_in[0];
    const float* W_ih_f = (const float*)d_in[2];
    const float* W_hh_f = (const float*)d_in[3];
    const float* b_ih_f = (const float*)d_in[4];
    const float* b_hh_f = (const float*)d_in[5];
    const float* W_ih_r = (const float*)d_in[6];
    const float* W_hh_r = (const float*)d_in[7];
    const float* b_ih_r = (const float*)d_in[8];
    const float* b_hh_r = (const float*)d_in[9];
    const float* W_act  = (const float*)d_in[10];
    const float* b_act  = (const float*)d_in[11];
    const float* W_val  = (const float*)d_in[12];
    const float* b_val  = (const float*)d_in[13];
    const float* W_out  = (const float*)d_in[14];
    const float* b_out  = (const float*)d_in[15];

    float* out = (float*)d_out;

    float *xf, *xr, *vals, *hid, *prm, *ro, *pw, *pr;
    cudaGetSymbolAddress((void**)&xf,   g_xproj_f);
    cudaGetSymbolAddress((void**)&xr,   g_xproj_r);
    cudaGetSymbolAddress((void**)&vals, g_values);
    cudaGetSymbolAddress((void**)&hid,  g_hidden);
    cudaGetSymbolAddress((void**)&prm,  g_params);
    cudaGetSymbolAddress((void**)&ro,   g_readout);
    cudaGetSymbolAddress((void**)&pw,   g_posw);
    cudaGetSymbolAddress((void**)&pr,   g_posr);

    bool full_out = (out_size >= OUT_TOTAL);

    // launch 0: fused input projections
    gemm_fused_in<<<dim3(10, N_ROWS / 128), 256>>>(
        inputs,
        W_ih_f, b_ih_f, b_hh_f,
        W_ih_r, b_ih_r, b_hh_r,
        W_val,  b_val,
        xf, xr, vals);

    // launch 1: LSTM recurrence (single-barrier, warp-local gate exchange)
    lstm_k<<<128, 256>>>(xf, xr, W_hh_f, W_hh_r, hid);

    // launch 2: action head
    act_k<<<128, 256>>>(hid, W_act, b_act, prm);

    // launch 3: fused tape machine (pos scan + sw + chunked tape scan)
    tape_k<<<128, 256>>>(vals, prm, pw, pr, ro,
                         full_out ? out + OUT_TAPE_OFF : nullptr,
                         full_out ? out + OUT_RPOS_OFF : nullptr,
                         full_out ? out + OUT_WPOS_OFF : nullptr);

    // launch 4: output projection straight into d_out
    gemm_k128<<<dim3(HID / 64, N_ROWS / 128), 256>>>(ro, W_out, b_out, out, HID);
}

// round 14
// speedup vs baseline: 1.0365x; 1.0365x over previous
#include <cuda_runtime.h>
#include <cuda_bf16.h>

// ---------------------------------------------------------------------------
// Problem constants (fixed by the dataset)
// ---------------------------------------------------------------------------
#define S_LEN   256
#define BSZ     64
#define IN_DIM  128
#define HID     128
#define NT      2
#define TAPELEN 128
#define DIM     64          // HID / NT
#define LH      64          // HID / 2
#define G4      256         // 4 * LH

#define N_ROWS  (S_LEN * BSZ)          // 16384

// d_out layout: outputs [S,B,HID], tape [TL,B,NT,DIM], rpos [TL,B,NT], wpos [TL,B,NT]
#define OUT_OUTPUTS_SZ  (S_LEN * BSZ * HID)                 // 2097152
#define OUT_TAPE_OFF    (OUT_OUTPUTS_SZ)
#define OUT_TAPE_SZ     (TAPELEN * BSZ * NT * DIM)          // 1048576
#define OUT_RPOS_OFF    (OUT_TAPE_OFF + OUT_TAPE_SZ)
#define OUT_POS_SZ      (TAPELEN * BSZ * NT)                // 16384
#define OUT_WPOS_OFF    (OUT_RPOS_OFF + OUT_POS_SZ)
#define OUT_TOTAL       (OUT_WPOS_OFF + OUT_POS_SZ)

typedef unsigned long long u64;

// ---------------------------------------------------------------------------
// f32x2 packed-math helpers (Blackwell FFMA2 path — PTX only)
// ---------------------------------------------------------------------------
__device__ __forceinline__ u64 pack2(float x, float y) {
    u64 r; asm("mov.b64 %0, {%1, %2};" : "=l"(r) : "f"(x), "f"(y)); return r;
}
__device__ __forceinline__ u64 dup2(float x) { return pack2(x, x); }
__device__ __forceinline__ void unpack2(u64 v, float& x, float& y) {
    asm("mov.b64 {%0, %1}, %2;" : "=f"(x), "=f"(y) : "l"(v));
}
__device__ __forceinline__ u64 ffma2(u64 a, u64 b, u64 c) {
    u64 d; asm("fma.rn.f32x2 %0, %1, %2, %3;" : "=l"(d) : "l"(a), "l"(b), "l"(c)); return d;
}
__device__ __forceinline__ u64 fadd2(u64 a, u64 b) {
    u64 d; asm("add.rn.f32x2 %0, %1, %2;" : "=l"(d) : "l"(a), "l"(b)); return d;
}
__device__ __forceinline__ u64 fmul2(u64 a, u64 b) {
    u64 d; asm("mul.rn.f32x2 %0, %1, %2;" : "=l"(d) : "l"(a), "l"(b)); return d;
}
__device__ __forceinline__ u64 shflx_u64(u64 v, int m) {
    float x, y; unpack2(v, x, y);
    x = __shfl_xor_sync(0xffffffffu, x, m);
    y = __shfl_xor_sync(0xffffffffu, y, m);
    return pack2(x, y);
}

__device__ __forceinline__ float sigmoidf_(float x) {
    return 1.0f / (1.0f + __expf(-x));
}
// tanh(x) = 2*sigmoid(2x) - 1  — MUFU-based, NaN-free at +/- inf
__device__ __forceinline__ float tanh_fast(float x) {
    return 2.0f / (1.0f + __expf(-2.0f * x)) - 1.0f;
}

// ---------------------------------------------------------------------------
// Scratch (device globals — no allocations allowed)
// ---------------------------------------------------------------------------
__device__ float g_xproj_f[N_ROWS * G4];     // 16.8 MB
__device__ float g_xproj_r[N_ROWS * G4];     // 16.8 MB
__device__ float g_values [N_ROWS * HID];    //  8.4 MB
__device__ float g_hidden [N_ROWS * HID];    //  8.4 MB
__device__ float g_params [N_ROWS * NT * 8]; //  1.0 MB
__device__ float g_readout[N_ROWS * HID];    //  8.4 MB
__device__ float g_posw  [BSZ * NT * S_LEN * TAPELEN];   // 16.8 MB
__device__ float g_posr  [BSZ * NT * S_LEN * TAPELEN];   // 16.8 MB

// ---------------------------------------------------------------------------
// GEMM core: C[M,N] = A[M,128] * B[N,128]^T + bias1[N] (+ bias2[N])
// ---------------------------------------------------------------------------
__device__ __forceinline__ void gemm_tile(
    const float* __restrict__ A, const float* __restrict__ B,
    const float* __restrict__ b1, const float* __restrict__ b2,
    float* __restrict__ C, int N, int row0, int col0)
{
    __shared__ __align__(16) float As[32][130];
    __shared__ __align__(16) float Bs[32][65];

    int tid = threadIdx.x;
    int tx = tid & 15;          // col group (4 cols)
    int ty = tid >> 4;          // row group (8 rows)

    const float4* A4 = (const float4*)A;
    const float4* B4 = (const float4*)B;

    u64 acc[4][4];
#pragma unroll
    for (int i = 0; i < 4; i++)
#pragma unroll
        for (int j = 0; j < 4; j++) acc[i][j] = 0ull;

#pragma unroll
    for (int kt = 0; kt < 4; kt++) {
#pragma unroll
        for (int rep = 0; rep < 4; rep++) {
            int e = tid + 256 * rep;
            int r = e >> 3, k4 = e & 7;
            float4 v = A4[(size_t)(row0 + r) * 32 + kt * 8 + k4];
            As[k4 * 4 + 0][r] = v.x; As[k4 * 4 + 1][r] = v.y;
            As[k4 * 4 + 2][r] = v.z; As[k4 * 4 + 3][r] = v.w;
        }
#pragma unroll
        for (int rep = 0; rep < 2; rep++) {
            int e = tid + 256 * rep;
            int r = e >> 3, k4 = e & 7;
            float4 v = B4[(size_t)(col0 + r) * 32 + kt * 8 + k4];
            Bs[k4 * 4 + 0][r] = v.x; Bs[k4 * 4 + 1][r] = v.y;
            Bs[k4 * 4 + 2][r] = v.z; Bs[k4 * 4 + 3][r] = v.w;
        }
        __syncthreads();

#pragma unroll
        for (int kk = 0; kk < 32; kk++) {
            u64 a2[4];
#pragma unroll
            for (int ip = 0; ip < 4; ip++)
                a2[ip] = *(const u64*)&As[kk][ty * 8 + 2 * ip];
#pragma unroll
            for (int j = 0; j < 4; j++) {
                u64 bd = dup2(Bs[kk][tx * 4 + j]);
#pragma unroll
                for (int ip = 0; ip < 4; ip++)
                    acc[ip][j] = ffma2(a2[ip], bd, acc[ip][j]);
            }
        }
        __syncthreads();
    }

#pragma unroll
    for (int j = 0; j < 4; j++) {
        int col = col0 + tx * 4 + j;
        float bv = b1[col] + (b2 ? b2[col] : 0.0f);
#pragma unroll
        for (int ip = 0; ip < 4; ip++) {
            float x, y; unpack2(acc[ip][j], x, y);
            int row = row0 + ty * 8 + 2 * ip;
            C[(size_t)row * N + col]       = x + bv;
            C[(size_t)(row + 1) * N + col] = y + bv;
        }
    }
}

// Fused input projections: 3 GEMMs (f-gates 256 cols, r-gates 256 cols, values 128 cols)
__global__ __launch_bounds__(256) void gemm_fused_in(
    const float* __restrict__ A,
    const float* __restrict__ Wf, const float* __restrict__ bf1, const float* __restrict__ bf2,
    const float* __restrict__ Wr, const float* __restrict__ br1, const float* __restrict__ br2,
    const float* __restrict__ Wv, const float* __restrict__ bv1,
    float* __restrict__ Cf, float* __restrict__ Cr, float* __restrict__ Cv)
{
    int cb = blockIdx.x;            // 0..9
    int row0 = blockIdx.y * 128;
    if (cb < 4)      gemm_tile(A, Wf, bf1, bf2,     Cf, G4,  row0, cb * 64);
    else if (cb < 8) gemm_tile(A, Wr, br1, br2,     Cr, G4,  row0, (cb - 4) * 64);
    else             gemm_tile(A, Wv, bv1, nullptr, Cv, HID, row0, (cb - 8) * 64);
}

__global__ __launch_bounds__(256) void gemm_k128(
    const float* __restrict__ A, const float* __restrict__ B,
    const float* __restrict__ b1, float* __restrict__ C, int N)
{
    gemm_tile(A, B, b1, nullptr, C, N, blockIdx.y * 128, blockIdx.x * 64);
}

// ---------------------------------------------------------------------------
// Kernel 2: bidirectional LSTM recurrence (proven r12 config — two barriers,
// act smem exchange, single-register xp prefetch).
// ---------------------------------------------------------------------------
__global__ __launch_bounds__(256) void lstm_k(
    const float* __restrict__ xpf, const float* __restrict__ xpr,
    const float* __restrict__ Whh_f, const float* __restrict__ Whh_r,
    float* __restrict__ hidden)
{
    int b   = blockIdx.x & 63;
    int dir = blockIdx.x >> 6;
    int j   = threadIdx.x;

    const float* Whh = dir ? Whh_r : Whh_f;
    const float* xp  = dir ? xpr   : xpf;

    u64 w2[32];
    const u64* wrow = (const u64*)(Whh + j * 64);
#pragma unroll
    for (int k = 0; k < 32; k++) w2[k] = wrow[k];

    __shared__ __align__(16) float h_sm[64];
    __shared__ float act[256];
    if (j < 64) h_sm[j] = 0.0f;
    float c = 0.0f;
    __syncthreads();

    const u64* h2 = (const u64*)h_sm;
    const float* xbase = xp + (size_t)b * G4 + j;

    int s   = dir ? (S_LEN - 1) : 0;
    int stp = dir ? -1 : 1;
    float gn = __ldg(&xbase[(size_t)s * (BSZ * G4)]);   // prefetch step 0

    for (int ss = 0; ss < S_LEN; ss++) {
        float g = gn;
        int s_cur = s;
        s += stp;
        if (ss + 1 < S_LEN)
            gn = __ldg(&xbase[(size_t)s * (BSZ * G4)]);  // prefetch next step

        u64 a0 = 0ull, a1 = 0ull, a2 = 0ull, a3 = 0ull;
#pragma unroll
        for (int k = 0; k < 32; k += 4) {
            a0 = ffma2(w2[k + 0], h2[k + 0], a0);
            a1 = ffma2(w2[k + 1], h2[k + 1], a1);
            a2 = ffma2(w2[k + 2], h2[k + 2], a2);
            a3 = ffma2(w2[k + 3], h2[k + 3], a3);
        }
        u64 at = fadd2(fadd2(a0, a1), fadd2(a2, a3));
        float sx, sy; unpack2(at, sx, sy);
        g += sx + sy;

        float av = (j >= 128 && j < 192) ? tanh_fast(g) : sigmoidf_(g);
        act[j] = av;
        __syncthreads();

        if (j < 64) {
            c = act[64 + j] * c + act[j] * act[128 + j];
            float h = act[192 + j] * tanh_fast(c);
            h_sm[j] = h;
            hidden[(size_t)(s_cur * BSZ + b) * HID + dir * 64 + j] = h;
        }
        __syncthreads();
    }
}

// ---------------------------------------------------------------------------
// Kernel 3: action head + nonlinearities. One thread per (row, tape).
// params[row][t][8] = {rd0,rd1,rd2, wd0,wd1,wd2, rw_read, rw_write}
// ---------------------------------------------------------------------------
__global__ __launch_bounds__(256) void act_k(
    const float* __restrict__ hidden, const float* __restrict__ Wact,
    const float* __restrict__ bact, float* __restrict__ params)
{
    int gt  = blockIdx.x * 256 + threadIdx.x;   // 0 .. 32767
    int row = gt >> 1;
    int t   = gt & 1;

    const float4* h4 = (const float4*)(hidden + (size_t)row * HID);
    const float4* w4 = (const float4*)Wact;

    float acc[8];
#pragma unroll
    for (int jj = 0; jj < 8; jj++) acc[jj] = 0.0f;

#pragma unroll 4
    for (int k4 = 0; k4 < 32; k4++) {
        float4 h = __ldg(&h4[k4]);
#pragma unroll
        for (int jj = 0; jj < 8; jj++) {
            float4 w = __ldg(&w4[(t * 8 + jj) * 32 + k4]);
            acc[jj] += h.x * w.x + h.y * w.y + h.z * w.z + h.w * w.w;
        }
    }
#pragma unroll
    for (int jj = 0; jj < 8; jj++) acc[jj] += bact[t * 8 + jj];

    float out[8];
    float m = fmaxf(acc[0], fmaxf(acc[1], acc[2]));
    float e0 = __expf(acc[0] - m), e1 = __expf(acc[1] - m), e2 = __expf(acc[2] - m);
    float inv = 1.0f / (e0 + e1 + e2);
    out[0] = e0 * inv; out[1] = e1 * inv; out[2] = e2 * inv;
    m = fmaxf(acc[3], fmaxf(acc[4], acc[5]));
    e0 = __expf(acc[3] - m); e1 = __expf(acc[4] - m); e2 = __expf(acc[5] - m);
    inv = 1.0f / (e0 + e1 + e2);
    out[3] = e0 * inv; out[4] = e1 * inv; out[5] = e2 * inv;
    out[6] = sigmoidf_(acc[6]);
    out[7] = sigmoidf_(acc[7]);

    float4* p4 = (float4*)(params + (size_t)gt * 8);
    p4[0] = make_float4(out[0], out[1], out[2], out[3]);
    p4[1] = make_float4(out[4], out[5], out[6], out[7]);
}

// ---------------------------------------------------------------------------
// Kernel 4: FUSED tape machine — one block per (b,t), 256 threads.
//   Phase A (warp 0): serial position scan -> global posw/posr (+ d_out).
//   Phase B: per step-pair p (s=2p): sw_s, sw_{s+1}, cww_p=<w_s,w_{s+1}>,
//            cwr_p=<w_s,r_{s+1}> — all position-only, parallel.
//   Phase C: 2-STEP-BLOCKED tape scan. Per pair, 4 dots vs the SAME tape
//            state + one butterfly; Gram corrections give step s+1 exactly:
//              d_s      = (v_s - A) rw1_s
//              ro_s     = (B + sw_s d_s) rw0_s
//              ow_{s+1} = C + cww d_s
//              d_{s+1}  = (v_{s+1} - ow_{s+1}) rw1_{s+1}
//              ro_{s+1} = (D + cwr d_s + sw_{s+1} d_{s+1}) rw0_{s+1}
//              T       += w_s d_s + w_{s+1} d_{s+1}
//            Serial chain per step is HALVED. w re-read from conflict-free
//            smem in the update (no wl register cache -> no spills).
// ---------------------------------------------------------------------------
#define TCHUNK 8
#define NCHUNK (S_LEN / TCHUNK)

__global__ __launch_bounds__(256) void tape_k(
    const float* __restrict__ values, const float* __restrict__ params,
    float* __restrict__ posw, float* __restrict__ posr,
    float* __restrict__ readouts, float* __restrict__ out_tape,
    float* __restrict__ out_rpos, float* __restrict__ out_wpos)
{
    int bt = blockIdx.x;            // b*2 + t
    int b  = bt >> 1;
    int t  = bt & 1;

    int tid  = threadIdx.x;         // 0..255
    int w    = tid >> 5;            // warp 0..7
    int lane = tid & 31;
    int cg   = lane >> 3;           // group within warp (0..3)
    int r    = lane & 7;            // lane-row within group
    int cp   = 4 * w + cg;          // column pair owned (0..31)

    __shared__ __align__(16) u64 pws[2][TCHUNK][TAPELEN];   // 16 KB (dup'd wpos)
    __shared__ __align__(16) u64 prs[2][TCHUNK][TAPELEN];   // 16 KB (dup'd rpos)
    __shared__ __align__(16) float vls[2][TCHUNK][64];      //  4 KB
    __shared__ float swv[S_LEN], rw0v[S_LEN], rw1v[S_LEN];  //  3 KB
    __shared__ float cwwv[S_LEN / 2], cwrv[S_LEN / 2];      //  1 KB
    // params overlay lives in pws[0] (8 KB) during phases A/B only
    float4* psm = (float4*)&pws[0][0][0];                   // [S_LEN*2]

    float* gw = posw + (size_t)bt * S_LEN * TAPELEN;
    float* gr = posr + (size_t)bt * S_LEN * TAPELEN;

    // ---- Phase A: stage params; warp 0 runs the serial position scan ----
    {
        const float4* pb = (const float4*)(params + (((size_t)b * 2) + t) * 8);
        for (int e = tid; e < S_LEN * 2; e += 256) {
            int s = e >> 1, half = e & 1;
            psm[s * 2 + half] = __ldg(&pb[(size_t)s * 256 + half]);
        }
    }
    __syncthreads();

    if (w == 0) {
        int pl0 = 4 * lane;
        float wp[4], rp[4];
#pragma unroll
        for (int i = 0; i < 4; i++) {
            float v = (lane == 0 && i == 0) ? 1.0f : 0.0f;
            wp[i] = v; rp[i] = v;
        }
        int src_up = (lane + 1) & 31;
        int src_dn = (lane - 1) & 31;

        for (int s = 0; s < S_LEN; s++) {
            *(float4*)(gw + (size_t)s * TAPELEN + pl0) = make_float4(wp[0], wp[1], wp[2], wp[3]);
            *(float4*)(gr + (size_t)s * TAPELEN + pl0) = make_float4(rp[0], rp[1], rp[2], rp[3]);

            float4 pp0 = psm[s * 2];
            float4 pp1 = psm[s * 2 + 1];

            float rtop = __shfl_sync(0xffffffffu, rp[0], src_up);   // rpos[pl0+4 mod 128]
            float rbot = __shfl_sync(0xffffffffu, rp[3], src_dn);   // rpos[pl0-1 mod 128]
            float rd0 = pp0.x, rd1 = pp0.y, rd2 = pp0.z;
            float wd0 = pp0.w, wd1 = pp1.x, wd2 = pp1.y;

            float prev = rbot;
#pragma unroll
            for (int i = 0; i < 4; i++) {
                float cur  = rp[i];
                float next = (i < 3) ? rp[i + 1] : rtop;
                // wpos'[l] = rpos[l+1]*wd0 + wpos[l]*wd1 + rpos[l-1]*wd2
                wp[i] = fmaf(next, wd0, fmaf(wp[i], wd1, prev * wd2));
                // rpos'[l] = rpos[l+1]*rd0 + rpos[l]*rd1 + rpos[l-1]*rd2
                rp[i] = fmaf(next, rd0, fmaf(cur,  rd1, prev * rd2));
                prev = cur;
            }
        }

        if (out_rpos) {
#pragma unroll
            for (int i = 0; i < 4; i++) {
                int l = pl0 + i;
                out_rpos[(size_t)(l * BSZ + b) * 2 + t] = rp[i];
                out_wpos[(size_t)(l * BSZ + b) * 2 + t] = wp[i];
            }
        }
    }
    __syncthreads();   // positions visible to all warps (in-block coherence)

    // ---- Phase B: per pair p: sw_s, sw_{s+1}, cww_p, cwr_p (16 pairs/warp) --
    for (int i = 0; i < 16; i++) {
        int p = w * 16 + i;
        int s = 2 * p;
        float4 ws  = *(const float4*)(gw + (size_t)s * TAPELEN + lane * 4);
        float4 rs  = *(const float4*)(gr + (size_t)s * TAPELEN + lane * 4);
        float4 ws1 = *(const float4*)(gw + (size_t)(s + 1) * TAPELEN + lane * 4);
        float4 rs1 = *(const float4*)(gr + (size_t)(s + 1) * TAPELEN + lane * 4);
        float dsw  = ws.x * rs.x  + ws.y * rs.y  + ws.z * rs.z  + ws.w * rs.w;
        float dsw1 = ws1.x * rs1.x + ws1.y * rs1.y + ws1.z * rs1.z + ws1.w * rs1.w;
        float dww  = ws.x * ws1.x + ws.y * ws1.y + ws.z * ws1.z + ws.w * ws1.w;
        float dwr  = ws.x * rs1.x + ws.y * rs1.y + ws.z * rs1.z + ws.w * rs1.w;
#pragma unroll
        for (int m = 1; m <= 16; m <<= 1) {
            dsw  += __shfl_xor_sync(0xffffffffu, dsw,  m);
            dsw1 += __shfl_xor_sync(0xffffffffu, dsw1, m);
            dww  += __shfl_xor_sync(0xffffffffu, dww,  m);
            dwr  += __shfl_xor_sync(0xffffffffu, dwr,  m);
        }
        if (lane == 0) {
            float4 p1a = psm[s * 2 + 1];
            float4 p1b = psm[(s + 1) * 2 + 1];
            swv[s] = dsw; swv[s + 1] = dsw1;
            cwwv[p] = dww; cwrv[p] = dwr;
            rw0v[s] = p1a.z; rw1v[s] = p1a.w;
            rw0v[s + 1] = p1b.z; rw1v[s + 1] = p1b.w;
        }
    }
    __syncthreads();   // psm (pws[0]) free to be overwritten from here

    // ---- Phase C: 2-step-blocked chunked tape scan ----
    u64 tp[16];
#pragma unroll
    for (int i = 0; i < 16; i++) tp[i] = 0ull;

    float* ro = readouts + (size_t)b * HID + t * 64 + 2 * cp;

    float4 wstg, rstg, vstg;
    int st_ls = tid >> 5, st_q = tid & 31;
    int sv_ls = tid >> 4, sv_q = tid & 15;

    // load + commit chunk 0
    {
        wstg = __ldg((const float4*)gw + tid);
        rstg = __ldg((const float4*)gr + tid);
        if (tid < 128)
            vstg = __ldg((const float4*)(values + ((size_t)sv_ls * BSZ + b) * HID + t * 64) + sv_q);
        u64* pwd = &pws[0][st_ls][4 * st_q];
        u64* prd = &prs[0][st_ls][4 * st_q];
        pwd[0] = dup2(wstg.x); pwd[1] = dup2(wstg.y); pwd[2] = dup2(wstg.z); pwd[3] = dup2(wstg.w);
        prd[0] = dup2(rstg.x); prd[1] = dup2(rstg.y); prd[2] = dup2(rstg.z); prd[3] = dup2(rstg.w);
        if (tid < 128) *(float4*)&vls[0][sv_ls][4 * sv_q] = vstg;
    }
    __syncthreads();

    for (int c = 0; c < NCHUNK; c++) {
        int buf = c & 1;

        // issue global loads for chunk c+1 (hidden under compute)
        if (c + 1 < NCHUNK) {
            size_t s0 = (size_t)(c + 1) * TCHUNK;
            wstg = __ldg((const float4*)(gw + s0 * TAPELEN) + tid);
            rstg = __ldg((const float4*)(gr + s0 * TAPELEN) + tid);
            if (tid < 128)
                vstg = __ldg((const float4*)(values + ((s0 + sv_ls) * BSZ + b) * HID + t * 64) + sv_q);
        }

        // compute 4 step-pairs from smem
#pragma unroll
        for (int lp = 0; lp < 4; lp++) {
            int ls = 2 * lp;
            int s  = c * TCHUNK + ls;
            int p  = s >> 1;

            u64 val_s  = *(const u64*)&vls[buf][ls][2 * cp];
            u64 val_s1 = *(const u64*)&vls[buf][ls + 1][2 * cp];

            // 4 dots against the SAME tape state
            u64 A = 0ull, B = 0ull, C = 0ull, D = 0ull;
#pragma unroll
            for (int k = 0; k < 8; k++) {
                ulonglong2 wv  = *(const ulonglong2*)&pws[buf][ls][16 * k + 2 * r];
                ulonglong2 rv  = *(const ulonglong2*)&prs[buf][ls][16 * k + 2 * r];
                ulonglong2 wv1 = *(const ulonglong2*)&pws[buf][ls + 1][16 * k + 2 * r];
                ulonglong2 rv1 = *(const ulonglong2*)&prs[buf][ls + 1][16 * k + 2 * r];
                A = ffma2(tp[2 * k], wv.x,  A); A = ffma2(tp[2 * k + 1], wv.y,  A);
                B = ffma2(tp[2 * k], rv.x,  B); B = ffma2(tp[2 * k + 1], rv.y,  B);
                C = ffma2(tp[2 * k], wv1.x, C); C = ffma2(tp[2 * k + 1], wv1.y, C);
                D = ffma2(tp[2 * k], rv1.x, D); D = ffma2(tp[2 * k + 1], rv1.y, D);
            }
            // one butterfly for all 4 (3 rounds over the 8-lane group)
#pragma unroll
            for (int m = 1; m <= 4; m <<= 1) {
                A = fadd2(A, shflx_u64(A, m));
                B = fadd2(B, shflx_u64(B, m));
                C = fadd2(C, shflx_u64(C, m));
                D = fadd2(D, shflx_u64(D, m));
            }

            float sw_s = swv[s], sw_s1 = swv[s + 1];
            float cww = cwwv[p], cwr = cwrv[p];

            // step s
            u64 d_s  = fmul2(ffma2(A, dup2(-1.0f), val_s), dup2(rw1v[s]));
            u64 ro_s = fmul2(ffma2(d_s, dup2(sw_s), B), dup2(rw0v[s]));
            // step s+1 via Gram corrections
            u64 ow1  = ffma2(d_s, dup2(cww), C);
            u64 d_s1 = fmul2(ffma2(ow1, dup2(-1.0f), val_s1), dup2(rw1v[s + 1]));
            u64 ro_s1 = ffma2(d_s1, dup2(sw_s1), ffma2(d_s, dup2(cwr), D));
            ro_s1 = fmul2(ro_s1, dup2(rw0v[s + 1]));

            if (r == 0) {
                float x, y;
                unpack2(ro_s, x, y);
                *(float2*)(ro + (size_t)s * (BSZ * HID)) = make_float2(x, y);
                unpack2(ro_s1, x, y);
                *(float2*)(ro + (size_t)(s + 1) * (BSZ * HID)) = make_float2(x, y);
            }

            // fused tape update for both steps (w re-read from smem)
#pragma unroll
            for (int k = 0; k < 8; k++) {
                ulonglong2 wv  = *(const ulonglong2*)&pws[buf][ls][16 * k + 2 * r];
                ulonglong2 wv1 = *(const ulonglong2*)&pws[buf][ls + 1][16 * k + 2 * r];
                tp[2 * k]     = ffma2(wv1.x, d_s1, ffma2(wv.x, d_s, tp[2 * k]));
                tp[2 * k + 1] = ffma2(wv1.y, d_s1, ffma2(wv.y, d_s, tp[2 * k + 1]));
            }
        }

        // commit staged chunk c+1 into the other buffer
        if (c + 1 < NCHUNK) {
            int nb = buf ^ 1;
            u64* pwd = &pws[nb][st_ls][4 * st_q];
            u64* prd = &prs[nb][st_ls][4 * st_q];
            pwd[0] = dup2(wstg.x); pwd[1] = dup2(wstg.y); pwd[2] = dup2(wstg.z); pwd[3] = dup2(wstg.w);
            prd[0] = dup2(rstg.x); prd[1] = dup2(rstg.y); prd[2] = dup2(rstg.z); prd[3] = dup2(rstg.w);
            if (tid < 128) *(float4*)&vls[nb][sv_ls][4 * sv_q] = vstg;
        }
        __syncthreads();
    }

    // final tape -> d_out  (level l = 16k + 2r + j, tp index 2k+j)
    if (out_tape) {
#pragma unroll
        for (int k = 0; k < 8; k++) {
#pragma unroll
            for (int j = 0; j < 2; j++) {
                int l = 16 * k + 2 * r + j;
                float x, y; unpack2(tp[2 * k + j], x, y);
                *(float2*)(out_tape + ((size_t)(l * BSZ + b) * 2 + t) * 64 + 2 * cp) =
                    make_float2(x, y);
            }
        }
    }
}

// ---------------------------------------------------------------------------
// Launcher — 5 launches; tape_k is launch index 3 (the one ncu captures).
// ---------------------------------------------------------------------------
extern "C" void kernel_launch(void* const* d_in, const int* in_sizes, int n_in,
                              void* d_out, int out_size)
{
    const float* inputs = (const float*)d_in[0];
    const float* W_ih_f = (const float*)d_in[2];
    const float* W_hh_f = (const float*)d_in[3];
    const float* b_ih_f = (const float*)d_in[4];
    const float* b_hh_f = (const float*)d_in[5];
    const float* W_ih_r = (const float*)d_in[6];
    const float* W_hh_r = (const float*)d_in[7];
    const float* b_ih_r = (const float*)d_in[8];
    const float* b_hh_r = (const float*)d_in[9];
    const float* W_act  = (const float*)d_in[10];
    const float* b_act  = (const float*)d_in[11];
    const float* W_val  = (const float*)d_in[12];
    const float* b_val  = (const float*)d_in[13];
    const float* W_out  = (const float*)d_in[14];
    const float* b_out  = (const float*)d_in[15];

    float* out = (float*)d_out;

    float *xf, *xr, *vals, *hid, *prm, *ro, *pw, *pr;
    cudaGetSymbolAddress((void**)&xf,   g_xproj_f);
    cudaGetSymbolAddress((void**)&xr,   g_xproj_r);
    cudaGetSymbolAddress((void**)&vals, g_values);
    cudaGetSymbolAddress((void**)&hid,  g_hidden);
    cudaGetSymbolAddress((void**)&prm,  g_params);
    cudaGetSymbolAddress((void**)&ro,   g_readout);
    cudaGetSymbolAddress((void**)&pw,   g_posw);
    cudaGetSymbolAddress((void**)&pr,   g_posr);

    bool full_out = (out_size >= OUT_TOTAL);

    // launch 0: fused input projections
    gemm_fused_in<<<dim3(10, N_ROWS / 128), 256>>>(
        inputs,
        W_ih_f, b_ih_f, b_hh_f,
        W_ih_r, b_ih_r, b_hh_r,
        W_val,  b_val,
        xf, xr, vals);

    // launch 1: LSTM recurrence (reverted to proven r12 design)
    lstm_k<<<128, 256>>>(xf, xr, W_hh_f, W_hh_r, hid);

    // launch 2: action head
    act_k<<<128, 256>>>(hid, W_act, b_act, prm);

    // launch 3: fused tape machine (pos scan + Gram aux + 2-step tape scan)
    tape_k<<<128, 256>>>(vals, prm, pw, pr, ro,
                         full_out ? out + OUT_TAPE_OFF : nullptr,
                         full_out ? out + OUT_RPOS_OFF : nullptr,
                         full_out ? out + OUT_WPOS_OFF : nullptr);

    // launch 4: output projection straight into d_out
    gemm_k128<<<dim3(HID / 64, N_ROWS / 128), 256>>>(ro, W_out, b_out, out, HID);
}

// round 15
// speedup vs baseline: 1.0468x; 1.0099x over previous
#include <cuda_runtime.h>
#include <cuda_bf16.h>

// ---------------------------------------------------------------------------
// Problem constants (fixed by the dataset)
// ---------------------------------------------------------------------------
#define S_LEN   256
#define BSZ     64
#define IN_DIM  128
#define HID     128
#define NT      2
#define TAPELEN 128
#define DIM     64          // HID / NT
#define LH      64          // HID / 2
#define G4      256         // 4 * LH

#define N_ROWS  (S_LEN * BSZ)          // 16384

// d_out layout: outputs [S,B,HID], tape [TL,B,NT,DIM], rpos [TL,B,NT], wpos [TL,B,NT]
#define OUT_OUTPUTS_SZ  (S_LEN * BSZ * HID)                 // 2097152
#define OUT_TAPE_OFF    (OUT_OUTPUTS_SZ)
#define OUT_TAPE_SZ     (TAPELEN * BSZ * NT * DIM)          // 1048576
#define OUT_RPOS_OFF    (OUT_TAPE_OFF + OUT_TAPE_SZ)
#define OUT_POS_SZ      (TAPELEN * BSZ * NT)                // 16384
#define OUT_WPOS_OFF    (OUT_RPOS_OFF + OUT_POS_SZ)
#define OUT_TOTAL       (OUT_WPOS_OFF + OUT_POS_SZ)

typedef unsigned long long u64;

// ---------------------------------------------------------------------------
// f32x2 packed-math helpers (Blackwell FFMA2 path — PTX only)
// ---------------------------------------------------------------------------
__device__ __forceinline__ u64 pack2(float x, float y) {
    u64 r; asm("mov.b64 %0, {%1, %2};" : "=l"(r) : "f"(x), "f"(y)); return r;
}
__device__ __forceinline__ u64 dup2(float x) { return pack2(x, x); }
__device__ __forceinline__ void unpack2(u64 v, float& x, float& y) {
    asm("mov.b64 {%0, %1}, %2;" : "=f"(x), "=f"(y) : "l"(v));
}
__device__ __forceinline__ u64 ffma2(u64 a, u64 b, u64 c) {
    u64 d; asm("fma.rn.f32x2 %0, %1, %2, %3;" : "=l"(d) : "l"(a), "l"(b), "l"(c)); return d;
}
__device__ __forceinline__ u64 fadd2(u64 a, u64 b) {
    u64 d; asm("add.rn.f32x2 %0, %1, %2;" : "=l"(d) : "l"(a), "l"(b)); return d;
}
__device__ __forceinline__ u64 fmul2(u64 a, u64 b) {
    u64 d; asm("mul.rn.f32x2 %0, %1, %2;" : "=l"(d) : "l"(a), "l"(b)); return d;
}
__device__ __forceinline__ u64 shflx_u64(u64 v, int m) {
    float x, y; unpack2(v, x, y);
    x = __shfl_xor_sync(0xffffffffu, x, m);
    y = __shfl_xor_sync(0xffffffffu, y, m);
    return pack2(x, y);
}

__device__ __forceinline__ float sigmoidf_(float x) {
    return 1.0f / (1.0f + __expf(-x));
}
// tanh(x) = 2*sigmoid(2x) - 1  — MUFU-based, NaN-free at +/- inf
__device__ __forceinline__ float tanh_fast(float x) {
    return 2.0f / (1.0f + __expf(-2.0f * x)) - 1.0f;
}

// ---------------------------------------------------------------------------
// Scratch (device globals — no allocations allowed)
// ---------------------------------------------------------------------------
__device__ float g_xproj_f[N_ROWS * G4];     // 16.8 MB
__device__ float g_xproj_r[N_ROWS * G4];     // 16.8 MB
__device__ float g_values [N_ROWS * HID];    //  8.4 MB
__device__ float g_hidden [N_ROWS * HID];    //  8.4 MB
__device__ float g_params [N_ROWS * NT * 8]; //  1.0 MB
__device__ float g_readout[N_ROWS * HID];    //  8.4 MB
__device__ float g_posw  [BSZ * NT * S_LEN * TAPELEN];   // 16.8 MB
__device__ float g_posr  [BSZ * NT * S_LEN * TAPELEN];   // 16.8 MB

// ---------------------------------------------------------------------------
// GEMM core: C[M,N] = A[M,128] * B[N,128]^T + bias1[N] (+ bias2[N])
// ---------------------------------------------------------------------------
__device__ __forceinline__ void gemm_tile(
    const float* __restrict__ A, const float* __restrict__ B,
    const float* __restrict__ b1, const float* __restrict__ b2,
    float* __restrict__ C, int N, int row0, int col0)
{
    __shared__ __align__(16) float As[32][130];
    __shared__ __align__(16) float Bs[32][65];

    int tid = threadIdx.x;
    int tx = tid & 15;          // col group (4 cols)
    int ty = tid >> 4;          // row group (8 rows)

    const float4* A4 = (const float4*)A;
    const float4* B4 = (const float4*)B;

    u64 acc[4][4];
#pragma unroll
    for (int i = 0; i < 4; i++)
#pragma unroll
        for (int j = 0; j < 4; j++) acc[i][j] = 0ull;

#pragma unroll
    for (int kt = 0; kt < 4; kt++) {
#pragma unroll
        for (int rep = 0; rep < 4; rep++) {
            int e = tid + 256 * rep;
            int r = e >> 3, k4 = e & 7;
            float4 v = A4[(size_t)(row0 + r) * 32 + kt * 8 + k4];
            As[k4 * 4 + 0][r] = v.x; As[k4 * 4 + 1][r] = v.y;
            As[k4 * 4 + 2][r] = v.z; As[k4 * 4 + 3][r] = v.w;
        }
#pragma unroll
        for (int rep = 0; rep < 2; rep++) {
            int e = tid + 256 * rep;
            int r = e >> 3, k4 = e & 7;
            float4 v = B4[(size_t)(col0 + r) * 32 + kt * 8 + k4];
            Bs[k4 * 4 + 0][r] = v.x; Bs[k4 * 4 + 1][r] = v.y;
            Bs[k4 * 4 + 2][r] = v.z; Bs[k4 * 4 + 3][r] = v.w;
        }
        __syncthreads();

#pragma unroll
        for (int kk = 0; kk < 32; kk++) {
            u64 a2[4];
#pragma unroll
            for (int ip = 0; ip < 4; ip++)
                a2[ip] = *(const u64*)&As[kk][ty * 8 + 2 * ip];
#pragma unroll
            for (int j = 0; j < 4; j++) {
                u64 bd = dup2(Bs[kk][tx * 4 + j]);
#pragma unroll
                for (int ip = 0; ip < 4; ip++)
                    acc[ip][j] = ffma2(a2[ip], bd, acc[ip][j]);
            }
        }
        __syncthreads();
    }

#pragma unroll
    for (int j = 0; j < 4; j++) {
        int col = col0 + tx * 4 + j;
        float bv = b1[col] + (b2 ? b2[col] : 0.0f);
#pragma unroll
        for (int ip = 0; ip < 4; ip++) {
            float x, y; unpack2(acc[ip][j], x, y);
            int row = row0 + ty * 8 + 2 * ip;
            C[(size_t)row * N + col]       = x + bv;
            C[(size_t)(row + 1) * N + col] = y + bv;
        }
    }
}

// Fused input projections: 3 GEMMs (f-gates 256 cols, r-gates 256 cols, values 128 cols)
__global__ __launch_bounds__(256) void gemm_fused_in(
    const float* __restrict__ A,
    const float* __restrict__ Wf, const float* __restrict__ bf1, const float* __restrict__ bf2,
    const float* __restrict__ Wr, const float* __restrict__ br1, const float* __restrict__ br2,
    const float* __restrict__ Wv, const float* __restrict__ bv1,
    float* __restrict__ Cf, float* __restrict__ Cr, float* __restrict__ Cv)
{
    int cb = blockIdx.x;            // 0..9
    int row0 = blockIdx.y * 128;
    if (cb < 4)      gemm_tile(A, Wf, bf1, bf2,     Cf, G4,  row0, cb * 64);
    else if (cb < 8) gemm_tile(A, Wr, br1, br2,     Cr, G4,  row0, (cb - 4) * 64);
    else             gemm_tile(A, Wv, bv1, nullptr, Cv, HID, row0, (cb - 8) * 64);
}

__global__ __launch_bounds__(256) void gemm_k128(
    const float* __restrict__ A, const float* __restrict__ B,
    const float* __restrict__ b1, float* __restrict__ C, int N)
{
    gemm_tile(A, B, b1, nullptr, C, N, blockIdx.y * 128, blockIdx.x * 64);
}

// ---------------------------------------------------------------------------
// Kernel 2: bidirectional LSTM recurrence (proven r12 config).
// ---------------------------------------------------------------------------
__global__ __launch_bounds__(256) void lstm_k(
    const float* __restrict__ xpf, const float* __restrict__ xpr,
    const float* __restrict__ Whh_f, const float* __restrict__ Whh_r,
    float* __restrict__ hidden)
{
    int b   = blockIdx.x & 63;
    int dir = blockIdx.x >> 6;
    int j   = threadIdx.x;

    const float* Whh = dir ? Whh_r : Whh_f;
    const float* xp  = dir ? xpr   : xpf;

    u64 w2[32];
    const u64* wrow = (const u64*)(Whh + j * 64);
#pragma unroll
    for (int k = 0; k < 32; k++) w2[k] = wrow[k];

    __shared__ __align__(16) float h_sm[64];
    __shared__ float act[256];
    if (j < 64) h_sm[j] = 0.0f;
    float c = 0.0f;
    __syncthreads();

    const u64* h2 = (const u64*)h_sm;
    const float* xbase = xp + (size_t)b * G4 + j;

    int s   = dir ? (S_LEN - 1) : 0;
    int stp = dir ? -1 : 1;
    float gn = __ldg(&xbase[(size_t)s * (BSZ * G4)]);   // prefetch step 0

    for (int ss = 0; ss < S_LEN; ss++) {
        float g = gn;
        int s_cur = s;
        s += stp;
        if (ss + 1 < S_LEN)
            gn = __ldg(&xbase[(size_t)s * (BSZ * G4)]);  // prefetch next step

        u64 a0 = 0ull, a1 = 0ull, a2 = 0ull, a3 = 0ull;
#pragma unroll
        for (int k = 0; k < 32; k += 4) {
            a0 = ffma2(w2[k + 0], h2[k + 0], a0);
            a1 = ffma2(w2[k + 1], h2[k + 1], a1);
            a2 = ffma2(w2[k + 2], h2[k + 2], a2);
            a3 = ffma2(w2[k + 3], h2[k + 3], a3);
        }
        u64 at = fadd2(fadd2(a0, a1), fadd2(a2, a3));
        float sx, sy; unpack2(at, sx, sy);
        g += sx + sy;

        float av = (j >= 128 && j < 192) ? tanh_fast(g) : sigmoidf_(g);
        act[j] = av;
        __syncthreads();

        if (j < 64) {
            c = act[64 + j] * c + act[j] * act[128 + j];
            float h = act[192 + j] * tanh_fast(c);
            h_sm[j] = h;
            hidden[(size_t)(s_cur * BSZ + b) * HID + dir * 64 + j] = h;
        }
        __syncthreads();
    }
}

// ---------------------------------------------------------------------------
// Kernel 3: action head + nonlinearities. One thread per (row, tape).
// ---------------------------------------------------------------------------
__global__ __launch_bounds__(256) void act_k(
    const float* __restrict__ hidden, const float* __restrict__ Wact,
    const float* __restrict__ bact, float* __restrict__ params)
{
    int gt  = blockIdx.x * 256 + threadIdx.x;   // 0 .. 32767
    int row = gt >> 1;
    int t   = gt & 1;

    const float4* h4 = (const float4*)(hidden + (size_t)row * HID);
    const float4* w4 = (const float4*)Wact;

    float acc[8];
#pragma unroll
    for (int jj = 0; jj < 8; jj++) acc[jj] = 0.0f;

#pragma unroll 4
    for (int k4 = 0; k4 < 32; k4++) {
        float4 h = __ldg(&h4[k4]);
#pragma unroll
        for (int jj = 0; jj < 8; jj++) {
            float4 w = __ldg(&w4[(t * 8 + jj) * 32 + k4]);
            acc[jj] += h.x * w.x + h.y * w.y + h.z * w.z + h.w * w.w;
        }
    }
#pragma unroll
    for (int jj = 0; jj < 8; jj++) acc[jj] += bact[t * 8 + jj];

    float out[8];
    float m = fmaxf(acc[0], fmaxf(acc[1], acc[2]));
    float e0 = __expf(acc[0] - m), e1 = __expf(acc[1] - m), e2 = __expf(acc[2] - m);
    float inv = 1.0f / (e0 + e1 + e2);
    out[0] = e0 * inv; out[1] = e1 * inv; out[2] = e2 * inv;
    m = fmaxf(acc[3], fmaxf(acc[4], acc[5]));
    e0 = __expf(acc[3] - m); e1 = __expf(acc[4] - m); e2 = __expf(acc[5] - m);
    inv = 1.0f / (e0 + e1 + e2);
    out[3] = e0 * inv; out[4] = e1 * inv; out[5] = e2 * inv;
    out[6] = sigmoidf_(acc[6]);
    out[7] = sigmoidf_(acc[7]);

    float4* p4 = (float4*)(params + (size_t)gt * 8);
    p4[0] = make_float4(out[0], out[1], out[2], out[3]);
    p4[1] = make_float4(out[4], out[5], out[6], out[7]);
}

// ---------------------------------------------------------------------------
// Kernel 4: FUSED tape machine — one block per (b,t), 512 threads (16 warps).
//   Phase A (warp 0): serial position scan -> global posw/posr (+ d_out).
//   Phase B: per step-pair p: sw_s, sw_{s+1}, cww, cwr (position-only).
//   Phase C: 2-step-blocked tape scan, DEDUPLICATED smem reads:
//     - warp w covers cps {2w, 2w+1}; half h = lane>>4 owns cp 2w+h fully;
//       lane r16 = lane&15 owns levels 16k + r16 (k=0..7).
//     - positions stored as plain f32; LDS.32 at [16k+r16]: 16 distinct
//       banks + exact-duplicate broadcast across halves -> 1 wavefront/load
//       (was 4 with the old 8-lane-group ulonglong2 layout: 768->256 wf/step).
//     - tape: 8 u64/lane; butterfly: 4 rounds (masks 1,2,4,8) within halves;
//       w floats cached in regs for the update (no smem re-read).
// ---------------------------------------------------------------------------
#define TCHUNK 8
#define NCHUNK (S_LEN / TCHUNK)

__global__ __launch_bounds__(512) void tape_k(
    const float* __restrict__ values, const float* __restrict__ params,
    float* __restrict__ posw, float* __restrict__ posr,
    float* __restrict__ readouts, float* __restrict__ out_tape,
    float* __restrict__ out_rpos, float* __restrict__ out_wpos)
{
    int bt = blockIdx.x;            // b*2 + t
    int b  = bt >> 1;
    int t  = bt & 1;

    int tid  = threadIdx.x;         // 0..511
    int w    = tid >> 5;            // warp 0..15
    int lane = tid & 31;
    int h    = lane >> 4;           // half (0..1) -> cp = 2w + h
    int r16  = lane & 15;           // lane-row within half
    int cp   = 2 * w + h;           // column pair owned (0..31)

    __shared__ __align__(16) float pws[2][TCHUNK][TAPELEN]; //  4 KB (f32 wpos)
    __shared__ __align__(16) float prs[2][TCHUNK][TAPELEN]; //  4 KB (f32 rpos)
    __shared__ __align__(16) float vls[2][TCHUNK][64];      //  2 KB
    __shared__ float swv[S_LEN], rw0v[S_LEN], rw1v[S_LEN];  //  3 KB
    __shared__ float cwwv[S_LEN / 2], cwrv[S_LEN / 2];      //  1 KB
    __shared__ __align__(16) float4 psm[S_LEN * 2];         //  8 KB

    float* gw = posw + (size_t)bt * S_LEN * TAPELEN;
    float* gr = posr + (size_t)bt * S_LEN * TAPELEN;

    // ---- Phase A: stage params (one float4 per thread); warp 0 pos scan ----
    {
        const float4* pb = (const float4*)(params + (((size_t)b * 2) + t) * 8);
        int s = tid >> 1, half = tid & 1;
        psm[tid] = __ldg(&pb[(size_t)s * 256 + half]);
    }
    __syncthreads();

    if (w == 0) {
        int pl0 = 4 * lane;
        float wp[4], rp[4];
#pragma unroll
        for (int i = 0; i < 4; i++) {
            float v = (lane == 0 && i == 0) ? 1.0f : 0.0f;
            wp[i] = v; rp[i] = v;
        }
        int src_up = (lane + 1) & 31;
        int src_dn = (lane - 1) & 31;

        for (int s = 0; s < S_LEN; s++) {
            *(float4*)(gw + (size_t)s * TAPELEN + pl0) = make_float4(wp[0], wp[1], wp[2], wp[3]);
            *(float4*)(gr + (size_t)s * TAPELEN + pl0) = make_float4(rp[0], rp[1], rp[2], rp[3]);

            float4 pp0 = psm[s * 2];
            float4 pp1 = psm[s * 2 + 1];

            float rtop = __shfl_sync(0xffffffffu, rp[0], src_up);   // rpos[pl0+4 mod 128]
            float rbot = __shfl_sync(0xffffffffu, rp[3], src_dn);   // rpos[pl0-1 mod 128]
            float rd0 = pp0.x, rd1 = pp0.y, rd2 = pp0.z;
            float wd0 = pp0.w, wd1 = pp1.x, wd2 = pp1.y;

            float prev = rbot;
#pragma unroll
            for (int i = 0; i < 4; i++) {
                float cur  = rp[i];
                float next = (i < 3) ? rp[i + 1] : rtop;
                // wpos'[l] = rpos[l+1]*wd0 + wpos[l]*wd1 + rpos[l-1]*wd2
                wp[i] = fmaf(next, wd0, fmaf(wp[i], wd1, prev * wd2));
                // rpos'[l] = rpos[l+1]*rd0 + rpos[l]*rd1 + rpos[l-1]*rd2
                rp[i] = fmaf(next, rd0, fmaf(cur,  rd1, prev * rd2));
                prev = cur;
            }
        }

        if (out_rpos) {
#pragma unroll
            for (int i = 0; i < 4; i++) {
                int l = pl0 + i;
                out_rpos[(size_t)(l * BSZ + b) * 2 + t] = rp[i];
                out_wpos[(size_t)(l * BSZ + b) * 2 + t] = wp[i];
            }
        }
    }
    __syncthreads();   // positions visible to all warps (in-block coherence)

    // ---- Phase B: per pair p: sw_s, sw_{s+1}, cww_p, cwr_p (8 pairs/warp) --
    for (int i = 0; i < 8; i++) {
        int p = w * 8 + i;
        int s = 2 * p;
        float4 ws  = *(const float4*)(gw + (size_t)s * TAPELEN + lane * 4);
        float4 rs  = *(const float4*)(gr + (size_t)s * TAPELEN + lane * 4);
        float4 ws1 = *(const float4*)(gw + (size_t)(s + 1) * TAPELEN + lane * 4);
        float4 rs1 = *(const float4*)(gr + (size_t)(s + 1) * TAPELEN + lane * 4);
        float dsw  = ws.x * rs.x  + ws.y * rs.y  + ws.z * rs.z  + ws.w * rs.w;
        float dsw1 = ws1.x * rs1.x + ws1.y * rs1.y + ws1.z * rs1.z + ws1.w * rs1.w;
        float dww  = ws.x * ws1.x + ws.y * ws1.y + ws.z * ws1.z + ws.w * ws1.w;
        float dwr  = ws.x * rs1.x + ws.y * rs1.y + ws.z * rs1.z + ws.w * rs1.w;
#pragma unroll
        for (int m = 1; m <= 16; m <<= 1) {
            dsw  += __shfl_xor_sync(0xffffffffu, dsw,  m);
            dsw1 += __shfl_xor_sync(0xffffffffu, dsw1, m);
            dww  += __shfl_xor_sync(0xffffffffu, dww,  m);
            dwr  += __shfl_xor_sync(0xffffffffu, dwr,  m);
        }
        if (lane == 0) {
            float4 p1a = psm[s * 2 + 1];
            float4 p1b = psm[(s + 1) * 2 + 1];
            swv[s] = dsw; swv[s + 1] = dsw1;
            cwwv[p] = dww; cwrv[p] = dwr;
            rw0v[s] = p1a.z; rw1v[s] = p1a.w;
            rw0v[s + 1] = p1b.z; rw1v[s + 1] = p1b.w;
        }
    }

    // ---- Phase C: 2-step-blocked chunked tape scan ----
    u64 tp[8];
#pragma unroll
    for (int i = 0; i < 8; i++) tp[i] = 0ull;

    float* ro = readouts + (size_t)b * HID + t * 64 + 2 * cp;

    // staging: threads 0..255 stage w float4s, 256..511 stage r float4s
    int sid   = tid & 255;
    int st_ls = sid >> 5, st_q = sid & 31;
    bool isw  = tid < 256;
    int sv_ls = tid >> 4, sv_q = tid & 15;   // tid<128 stages values

    float4 stg, vstg;
    stg = __ldg((const float4*)(isw ? gw : gr) + sid);
    if (tid < 128)
        vstg = __ldg((const float4*)(values + ((size_t)sv_ls * BSZ + b) * HID + t * 64) + sv_q);
    if (isw) *(float4*)&pws[0][st_ls][4 * st_q] = stg;
    else     *(float4*)&prs[0][st_ls][4 * st_q] = stg;
    if (tid < 128) *(float4*)&vls[0][sv_ls][4 * sv_q] = vstg;
    __syncthreads();

    for (int c = 0; c < NCHUNK; c++) {
        int buf = c & 1;

        // issue global loads for chunk c+1 (hidden under compute)
        if (c + 1 < NCHUNK) {
            size_t s0 = (size_t)(c + 1) * TCHUNK;
            stg = __ldg((const float4*)((isw ? gw : gr) + s0 * TAPELEN) + sid);
            if (tid < 128)
                vstg = __ldg((const float4*)(values + ((s0 + sv_ls) * BSZ + b) * HID + t * 64) + sv_q);
        }

        // compute 4 step-pairs from smem
#pragma unroll
        for (int lp = 0; lp < 4; lp++) {
            int ls = 2 * lp;
            int s  = c * TCHUNK + ls;
            int p  = s >> 1;

            u64 val_s  = *(const u64*)&vls[buf][ls][2 * cp];
            u64 val_s1 = *(const u64*)&vls[buf][ls + 1][2 * cp];

            // conflict-free interleaved position loads (level = 16k + r16)
            float wf0[8], rf0[8], wf1[8], rf1[8];
#pragma unroll
            for (int k = 0; k < 8; k++) {
                wf0[k] = pws[buf][ls][16 * k + r16];
                rf0[k] = prs[buf][ls][16 * k + r16];
                wf1[k] = pws[buf][ls + 1][16 * k + r16];
                rf1[k] = prs[buf][ls + 1][16 * k + r16];
            }

            // 4 dots against the SAME tape state
            u64 A = 0ull, B = 0ull, C = 0ull, D = 0ull;
#pragma unroll
            for (int k = 0; k < 8; k++) {
                A = ffma2(tp[k], dup2(wf0[k]), A);
                B = ffma2(tp[k], dup2(rf0[k]), B);
                C = ffma2(tp[k], dup2(wf1[k]), C);
                D = ffma2(tp[k], dup2(rf1[k]), D);
            }
            // butterfly over the 16-lane half (4 rounds)
#pragma unroll
            for (int m = 1; m <= 8; m <<= 1) {
                A = fadd2(A, shflx_u64(A, m));
                B = fadd2(B, shflx_u64(B, m));
                C = fadd2(C, shflx_u64(C, m));
                D = fadd2(D, shflx_u64(D, m));
            }

            float sw_s = swv[s], sw_s1 = swv[s + 1];
            float cww = cwwv[p], cwr = cwrv[p];

            // step s
            u64 d_s  = fmul2(ffma2(A, dup2(-1.0f), val_s), dup2(rw1v[s]));
            u64 ro_s = fmul2(ffma2(d_s, dup2(sw_s), B), dup2(rw0v[s]));
            // step s+1 via Gram corrections
            u64 ow1  = ffma2(d_s, dup2(cww), C);
            u64 d_s1 = fmul2(ffma2(ow1, dup2(-1.0f), val_s1), dup2(rw1v[s + 1]));
            u64 ro_s1 = ffma2(d_s1, dup2(sw_s1), ffma2(d_s, dup2(cwr), D));
            ro_s1 = fmul2(ro_s1, dup2(rw0v[s + 1]));

            if (r16 == 0) {
                float x, y;
                unpack2(ro_s, x, y);
                *(float2*)(ro + (size_t)s * (BSZ * HID)) = make_float2(x, y);
                unpack2(ro_s1, x, y);
                *(float2*)(ro + (size_t)(s + 1) * (BSZ * HID)) = make_float2(x, y);
            }

            // fused tape update for both steps (w cached in registers)
#pragma unroll
            for (int k = 0; k < 8; k++)
                tp[k] = ffma2(dup2(wf1[k]), d_s1, ffma2(dup2(wf0[k]), d_s, tp[k]));
        }

        // commit staged chunk c+1 into the other buffer
        if (c + 1 < NCHUNK) {
            int nb = buf ^ 1;
            if (isw) *(float4*)&pws[nb][st_ls][4 * st_q] = stg;
            else     *(float4*)&prs[nb][st_ls][4 * st_q] = stg;
            if (tid < 128) *(float4*)&vls[nb][sv_ls][4 * sv_q] = vstg;
        }
        __syncthreads();
    }

    // final tape -> d_out  (level l = 16k + r16, tp index k)
    if (out_tape) {
#pragma unroll
        for (int k = 0; k < 8; k++) {
            int l = 16 * k + r16;
            float x, y; unpack2(tp[k], x, y);
            *(float2*)(out_tape + ((size_t)(l * BSZ + b) * 2 + t) * 64 + 2 * cp) =
                make_float2(x, y);
        }
    }
}

// ---------------------------------------------------------------------------
// Launcher — 5 launches; tape_k is launch index 3 (the one ncu captures).
// ---------------------------------------------------------------------------
extern "C" void kernel_launch(void* const* d_in, const int* in_sizes, int n_in,
                              void* d_out, int out_size)
{
    const float* inputs = (const float*)d_in[0];
    const float* W_ih_f = (const float*)d_in[2];
    const float* W_hh_f = (const float*)d_in[3];
    const float* b_ih_f = (const float*)d_in[4];
    const float* b_hh_f = (const float*)d_in[5];
    const float* W_ih_r = (const float*)d_in[6];
    const float* W_hh_r = (const float*)d_in[7];
    const float* b_ih_r = (const float*)d_in[8];
    const float* b_hh_r = (const float*)d_in[9];
    const float* W_act  = (const float*)d_in[10];
    const float* b_act  = (const float*)d_in[11];
    const float* W_val  = (const float*)d_in[12];
    const float* b_val  = (const float*)d_in[13];
    const float* W_out  = (const float*)d_in[14];
    const float* b_out  = (const float*)d_in[15];

    float* out = (float*)d_out;

    float *xf, *xr, *vals, *hid, *prm, *ro, *pw, *pr;
    cudaGetSymbolAddress((void**)&xf,   g_xproj_f);
    cudaGetSymbolAddress((void**)&xr,   g_xproj_r);
    cudaGetSymbolAddress((void**)&vals, g_values);
    cudaGetSymbolAddress((void**)&hid,  g_hidden);
    cudaGetSymbolAddress((void**)&prm,  g_params);
    cudaGetSymbolAddress((void**)&ro,   g_readout);
    cudaGetSymbolAddress((void**)&pw,   g_posw);
    cudaGetSymbolAddress((void**)&pr,   g_posr);

    bool full_out = (out_size >= OUT_TOTAL);

    // launch 0: fused input projections
    gemm_fused_in<<<dim3(10, N_ROWS / 128), 256>>>(
        inputs,
        W_ih_f, b_ih_f, b_hh_f,
        W_ih_r, b_ih_r, b_hh_r,
        W_val,  b_val,
        xf, xr, vals);

    // launch 1: LSTM recurrence
    lstm_k<<<128, 256>>>(xf, xr, W_hh_f, W_hh_r, hid);

    // launch 2: action head
    act_k<<<128, 256>>>(hid, W_act, b_act, prm);

    // launch 3: fused tape machine (512 threads, dedup'd position reads)
    tape_k<<<128, 512>>>(vals, prm, pw, pr, ro,
                         full_out ? out + OUT_TAPE_OFF : nullptr,
                         full_out ? out + OUT_RPOS_OFF : nullptr,
                         full_out ? out + OUT_WPOS_OFF : nullptr);

    // launch 4: output projection straight into d_out
    gemm_k128<<<dim3(HID / 64, N_ROWS / 128), 256>>>(ro, W_out, b_out, out, HID);
}